// round 10
// baseline (speedup 1.0000x reference)
#include <cuda_runtime.h>
#include <cuda_fp16.h>
#include <math.h>
#include <stdint.h>

// ---------------- problem constants ----------------
#define T_TOK   2048
#define DDIM    768
#define HDIM    1536
#define NEXP    16
#define NSLOT   4
#define TOTSLOT (T_TOK*NSLOT)
#define LN_EPS  1e-5f

#define IX_X    0
#define IX_GW   1
#define IX_GB   2
#define IX_F1W  3
#define IX_F1B  4
#define IX_LNW  5
#define IX_LNB  6
#define IX_F2W  7
#define IX_F2B  8

// ---------------- device scratch ----------------
__device__ const float* g_p[9];
__device__ int   g_ecnt[NEXP];
__device__ int   g_wq[2];                 // work-queue counters (fc1, fc2)
__device__ int   g_elist[NEXP * T_TOK];
__device__ __align__(16) float  g_wslot[TOTSLOT];
__device__ int   g_eslot[TOTSLOT];
__device__ __align__(16) float  g_hbuf[(size_t)TOTSLOT * HDIM];          // fc1 out fp32
__device__ __align__(16) __half g_hh[(size_t)TOTSLOT * HDIM];            // LN out fp16
__device__ __align__(16) float  g_ybuf[(size_t)TOTSLOT * DDIM];          // fc2 out fp32
__device__ __align__(16) __half g_xh[(size_t)T_TOK * DDIM];              // x fp16
__device__ __align__(16) __half g_w1h[(size_t)NEXP * DDIM * HDIM];
__device__ __align__(16) __half g_w2h[(size_t)NEXP * HDIM * DDIM];

struct InArgs { const float* p[9]; int sz[9]; int n; };

// ---------------- classify inputs (warp-parallel value scans) ----------------
__global__ void classify_kernel(InArgs a) {
    int lane = threadIdx.x;
    if (lane < NEXP) g_ecnt[lane] = 0;
    if (lane < 2)    g_wq[lane] = 0;

    __shared__ int nzf[9], onesf[9];
    for (int i = 0; i < 9; i++) {
        bool nz = false, ones = true;
        if (i < a.n) {
            for (int j = lane; j < 256; j += 32)
                if (a.p[i][j] != 0.f) { nz = true; break; }
            for (int j = lane; j < 64; j += 32)
                if (a.p[i][j] != 1.0f) { ones = false; break; }
        }
        unsigned nzb = __ballot_sync(0xffffffffu, nz);
        unsigned onb = __ballot_sync(0xffffffffu, !ones);
        if (lane == 0) { nzf[i] = (nzb != 0); onesf[i] = (onb == 0); }
    }
    __syncwarp();
    if (lane != 0) return;

    bool used[9]; const float* P[9];
#pragma unroll
    for (int i = 0; i < 9; i++) { used[i] = false; P[i] = nullptr; }

    for (int i = 0; i < a.n && i < 9; i++) {
        if (a.sz[i] == T_TOK * DDIM)      { P[IX_X]  = a.p[i]; used[i] = true; }
        else if (a.sz[i] == NEXP)         { P[IX_GB] = a.p[i]; used[i] = true; }
    }
    for (int i = 0; i < a.n && i < 9; i++) {
        if (!used[i] && a.sz[i] == NEXP * DDIM * HDIM) {
            if (!P[IX_F1W]) P[IX_F1W] = a.p[i]; else P[IX_F2W] = a.p[i];
            used[i] = true;
        }
    }
    for (int i = 0; i < a.n && i < 9; i++) {
        if (!used[i] && a.sz[i] == DDIM * NEXP) {
            if (nzf[i] && !P[IX_GW]) P[IX_GW] = a.p[i];
            else if (!P[IX_F2B])     P[IX_F2B] = a.p[i];
            else                     P[IX_GW]  = a.p[i];
            used[i] = true;
        }
    }
    for (int i = 0; i < a.n && i < 9; i++) {
        if (!used[i] && a.sz[i] == NEXP * HDIM) {
            if (onesf[i] && !P[IX_LNW]) P[IX_LNW] = a.p[i];
            else if (!P[IX_F1B])        P[IX_F1B] = a.p[i];
            else if (!P[IX_LNB])        P[IX_LNB] = a.p[i];
            else                        P[IX_LNW] = a.p[i];
            used[i] = true;
        }
    }
#pragma unroll
    for (int k = 0; k < 9; k++) if (!P[k]) P[k] = a.p[k];
#pragma unroll
    for (int k = 0; k < 9; k++) g_p[k] = P[k];
}

// ---------------- gating: one warp per token (full fp32) ----------------
__global__ __launch_bounds__(256) void gate_kernel()
{
    const float* x  = g_p[IX_X];
    const float* gw = g_p[IX_GW];
    const float* gb = g_p[IX_GB];

    int gtid = blockIdx.x * blockDim.x + threadIdx.x;
    int t    = gtid >> 5;
    int lane = gtid & 31;
    if (t >= T_TOK) return;

    float acc[NEXP];
#pragma unroll
    for (int e = 0; e < NEXP; e++) acc[e] = 0.f;

    const float* xr = x + (size_t)t * DDIM;
    for (int d = lane; d < DDIM; d += 32) {
        float xv = xr[d];
        const float* wr = gw + d * NEXP;
#pragma unroll
        for (int e = 0; e < NEXP; e++) acc[e] += xv * wr[e];
    }
#pragma unroll
    for (int e = 0; e < NEXP; e++) {
#pragma unroll
        for (int off = 16; off; off >>= 1)
            acc[e] += __shfl_xor_sync(0xffffffffu, acc[e], off);
    }

    if (lane == 0) {
        float s[NEXP];
#pragma unroll
        for (int e = 0; e < NEXP; e++) s[e] = acc[e] + gb[e];
        s[0] = -1e9f;
        float mx = s[0];
#pragma unroll
        for (int e = 1; e < NEXP; e++) mx = fmaxf(mx, s[e]);
        float p[NEXP]; float sum = 0.f;
#pragma unroll
        for (int e = 0; e < NEXP; e++) { p[e] = expf(s[e] - mx); sum += p[e]; }
        float inv = 1.f / sum;
#pragma unroll
        for (int e = 0; e < NEXP; e++) p[e] *= inv;

        int base = t * NSLOT;
        g_wslot[base] = 1.0f;
        g_eslot[base] = 0;
        int pos = atomicAdd(&g_ecnt[0], 1);
        g_elist[0 * T_TOK + pos] = base;

        for (int k = 0; k < 3; k++) {
            int bi = -1; float bv = -1.f;
#pragma unroll
            for (int e = 0; e < NEXP; e++)
                if (p[e] > bv) { bv = p[e]; bi = e; }
            p[bi] = -2.f;
            g_wslot[base + 1 + k] = bv;
            g_eslot[base + 1 + k] = bi;
            int pp = atomicAdd(&g_ecnt[bi], 1);
            g_elist[bi * T_TOK + pp] = base + 1 + k;
        }
    }
}

// ---------------- convert weights + x to fp16 (fused, streaming reads) -------
__device__ __forceinline__ uint2 f4_to_h4(float4 v) {
    __half2 lo = __floats2half2_rn(v.x, v.y);
    __half2 hi = __floats2half2_rn(v.z, v.w);
    return make_uint2(*(uint32_t*)&lo, *(uint32_t*)&hi);
}
#define WQUARTS (NEXP * DDIM * HDIM / 4)
#define XQUARTS (T_TOK * DDIM / 4)
__global__ __launch_bounds__(256) void cvt_all_kernel()
{
    int i = blockIdx.x * blockDim.x + threadIdx.x;
    if (i < WQUARTS) {
        float4 v = __ldcs((const float4*)g_p[IX_F1W] + i);
        ((uint2*)g_w1h)[i] = f4_to_h4(v);
    } else if (i < 2 * WQUARTS) {
        int j = i - WQUARTS;
        float4 v = __ldcs((const float4*)g_p[IX_F2W] + j);
        ((uint2*)g_w2h)[j] = f4_to_h4(v);
    } else if (i < 2 * WQUARTS + XQUARTS) {
        int j = i - 2 * WQUARTS;
        float4 v = ((const float4*)g_p[IX_X])[j];
        ((uint2*)g_xh)[j] = f4_to_h4(v);
    }
}

// ---------------- fp16 MMA helpers ----------------
__device__ __forceinline__ void ldsm_x4(uint32_t& r0, uint32_t& r1, uint32_t& r2, uint32_t& r3,
                                        uint32_t addr) {
    asm volatile("ldmatrix.sync.aligned.m8n8.x4.shared.b16 {%0,%1,%2,%3}, [%4];"
                 : "=r"(r0), "=r"(r1), "=r"(r2), "=r"(r3) : "r"(addr));
}
__device__ __forceinline__ void ldsm_x4t(uint32_t& r0, uint32_t& r1, uint32_t& r2, uint32_t& r3,
                                         uint32_t addr) {
    asm volatile("ldmatrix.sync.aligned.m8n8.x4.trans.shared.b16 {%0,%1,%2,%3}, [%4];"
                 : "=r"(r0), "=r"(r1), "=r"(r2), "=r"(r3) : "r"(addr));
}
__device__ __forceinline__ void mma_f16(float c[4],
    uint32_t a0, uint32_t a1, uint32_t a2, uint32_t a3,
    uint32_t b0, uint32_t b1)
{
    asm volatile(
        "mma.sync.aligned.m16n8k16.row.col.f32.f16.f16.f32 "
        "{%0,%1,%2,%3}, {%4,%5,%6,%7}, {%8,%9}, {%0,%1,%2,%3};"
        : "+f"(c[0]), "+f"(c[1]), "+f"(c[2]), "+f"(c[3])
        : "r"(a0), "r"(a1), "r"(a2), "r"(a3), "r"(b0), "r"(b1));
}
__device__ __forceinline__ void cp16(uint32_t dst, const void* src) {
    asm volatile("cp.async.ca.shared.global [%0], [%1], 16;\n" :: "r"(dst), "l"(src));
}
#define CP_COMMIT() asm volatile("cp.async.commit_group;\n" ::: "memory")
#define CP_WAIT0()  asm volatile("cp.async.wait_group 0;\n" ::: "memory")
#define CP_WAIT1()  asm volatile("cp.async.wait_group 1;\n" ::: "memory")

// ---------------- persistent gathered expert GEMM ---------------------------
// block tile 128x256, BK=64, 3-stage cp.async; 8 warps as 2m x 4n (64x64 warp tile).
// Work-stealing over (e, mt, nt) tiles via global atomic counter.
#define BM 128
#define BN 256
#define BK 64
#define MT 16         // mtiles per expert (worst case)
#define AST 72        // A row stride (halfs)
#define BST 264       // B row stride (halfs)
#define NSTG 3
#define A_STG (BM * AST)                 // 9216 halfs
#define B_STG (BK * BST)                 // 16896 halfs
#define STG_H (A_STG + B_STG)            // 26112 halfs
#define GEMM_SMEM (NSTG * STG_H * 2 + BM * 4)
#define NPERSIST 152

__global__ __launch_bounds__(256, 1) void expert_gemm_fp16(int which)
{
    extern __shared__ __half smh[];
    int* s_entry = (int*)(smh + NSTG * STG_H);

    const __half* Asrc; const __half* W; const float* bias;
    int KDIM, NDIM, in_is_token, ntiles;
    if (which == 0) {
        Asrc = g_xh; W = g_w1h; bias = g_p[IX_F1B];
        KDIM = DDIM; NDIM = HDIM; in_is_token = 1; ntiles = HDIM / BN;  // 6
    } else {
        Asrc = g_hh; W = g_w2h; bias = g_p[IX_F2B];
        KDIM = HDIM; NDIM = DDIM; in_is_token = 0; ntiles = DDIM / BN;  // 3
    }
    int total_items = NEXP * MT * ntiles;

    int tid  = threadIdx.x;
    int lane = tid & 31;
    int wid  = tid >> 5;
    int wm   = wid >> 2;     // 0..1 -> 64 rows
    int wn   = wid & 3;      // 0..3 -> 64 cols
    int lr = lane & 15;
    int lc = lane >> 4;
    int qrow = lane >> 2;
    int qcol = lane & 3;

    uint32_t sbase = (uint32_t)__cvta_generic_to_shared(smh);
    uint32_t aOff[4];
#pragma unroll
    for (int mf = 0; mf < 4; mf++)
        aOff[mf] = (uint32_t)(((wm * 64 + mf * 16 + lr) * AST + lc * 8) * 2);
    uint32_t bOff = (uint32_t)((A_STG + lr * BST + wn * 64 + lc * 8) * 2);

    int a_rb = tid >> 3;
    int a_j  = (tid & 7) * 8;
    int b_rb = tid >> 5;
    int b_j  = (tid & 31) * 8;
    uint32_t bDst[8];
#pragma unroll
    for (int q = 0; q < 8; q++)
        bDst[q] = (uint32_t)(A_STG + (b_rb + 8 * q) * BST + b_j) * 2;
    uint32_t aDstBase[4];
#pragma unroll
    for (int q = 0; q < 4; q++)
        aDstBase[q] = (uint32_t)((a_rb + 32 * q) * AST + a_j) * 2;

    int nk = KDIM / BK;

    __shared__ int s_item;

    for (;;) {
        // ---- pop next work item ----
        if (tid == 0) s_item = atomicAdd(&g_wq[which], 1);
        __syncthreads();
        int item = s_item;
        if (item >= total_items) return;

        int e   = item / (MT * ntiles);
        int rem = item % (MT * ntiles);
        int mt  = rem / ntiles;
        int nt  = rem % ntiles;
        int cnt = g_ecnt[e];
        int m0  = mt * BM;
        if (m0 >= cnt) { __syncthreads(); continue; }
        int n0  = nt * BN;

        if (tid < BM) {
            int gm = m0 + tid;
            s_entry[tid] = (gm < cnt) ? g_elist[e * T_TOK + gm] : -1;
        }
        __syncthreads();

        // per-item A pointers
        const __half* aptr[4];
#pragma unroll
        for (int q = 0; q < 4; q++) {
            int row = a_rb + 32 * q;
            int ent = s_entry[row];
            int ar  = (ent >= 0) ? (in_is_token ? (ent >> 2) : ent) : 0;
            aptr[q] = Asrc + (size_t)ar * KDIM + a_j;
        }
        const __half* wrow = W + (size_t)e * KDIM * NDIM + n0 + b_j;

        float acc[4][8][4];
#pragma unroll
        for (int i = 0; i < 4; i++)
#pragma unroll
            for (int j = 0; j < 8; j++)
#pragma unroll
                for (int q = 0; q < 4; q++) acc[i][j][q] = 0.f;

        // prologue: tiles 0, 1
#pragma unroll
        for (int s = 0; s < NSTG - 1; s++) {
            uint32_t st = sbase + (uint32_t)(s * STG_H * 2);
            int k0 = s * BK;
#pragma unroll
            for (int q = 0; q < 4; q++) cp16(st + aDstBase[q], aptr[q] + k0);
#pragma unroll
            for (int q = 0; q < 8; q++)
                cp16(st + bDst[q], wrow + (size_t)(k0 + b_rb + 8 * q) * NDIM);
            CP_COMMIT();
        }

        for (int kt = 0; kt < nk; kt++) {
            if (kt + 1 < nk) { CP_WAIT1(); } else { CP_WAIT0(); }
            __syncthreads();

            int nxt = kt + NSTG - 1;
            if (nxt < nk) {
                uint32_t st = sbase + (uint32_t)((nxt % NSTG) * STG_H * 2);
                int k0 = nxt * BK;
#pragma unroll
                for (int q = 0; q < 4; q++) cp16(st + aDstBase[q], aptr[q] + k0);
#pragma unroll
                for (int q = 0; q < 8; q++)
                    cp16(st + bDst[q], wrow + (size_t)(k0 + b_rb + 8 * q) * NDIM);
                CP_COMMIT();
            }

            uint32_t stg = sbase + (uint32_t)((kt % NSTG) * STG_H * 2);

            uint32_t af[2][4][4], bf[2][4][4];
#pragma unroll
            for (int mf = 0; mf < 4; mf++)
                ldsm_x4(af[0][mf][0], af[0][mf][1], af[0][mf][2], af[0][mf][3],
                        stg + aOff[mf]);
#pragma unroll
            for (int ng = 0; ng < 4; ng++)
                ldsm_x4t(bf[0][ng][0], bf[0][ng][1], bf[0][ng][2], bf[0][ng][3],
                         stg + bOff + (uint32_t)(ng * 32));

#pragma unroll
            for (int ks = 0; ks < 4; ks++) {
                int cb = ks & 1;
                if (ks < 3) {
                    int nb = cb ^ 1;
                    uint32_t ka = (uint32_t)((ks + 1) * 32);
                    uint32_t kb = (uint32_t)((ks + 1) * 16 * BST * 2);
#pragma unroll
                    for (int mf = 0; mf < 4; mf++)
                        ldsm_x4(af[nb][mf][0], af[nb][mf][1], af[nb][mf][2], af[nb][mf][3],
                                stg + aOff[mf] + ka);
#pragma unroll
                    for (int ng = 0; ng < 4; ng++)
                        ldsm_x4t(bf[nb][ng][0], bf[nb][ng][1], bf[nb][ng][2], bf[nb][ng][3],
                                 stg + bOff + kb + (uint32_t)(ng * 32));
                }
#pragma unroll
                for (int mf = 0; mf < 4; mf++)
#pragma unroll
                    for (int nf = 0; nf < 8; nf++) {
                        int ng = nf >> 1, hh = (nf & 1) * 2;
                        mma_f16(acc[mf][nf],
                                af[cb][mf][0], af[cb][mf][1], af[cb][mf][2], af[cb][mf][3],
                                bf[cb][ng][hh], bf[cb][ng][hh + 1]);
                    }
            }
        }

        // ---- epilogue ----
        const float* brow = bias + (size_t)e * NDIM + n0;
#pragma unroll
        for (int mf = 0; mf < 4; mf++) {
            int r0 = wm * 64 + mf * 16 + qrow;
#pragma unroll
            for (int half = 0; half < 2; half++) {
                int r = r0 + half * 8;
                int ent = s_entry[r];
                if (ent < 0) continue;
                if (which == 0) {
                    float* orow = g_hbuf + (size_t)ent * HDIM + n0;
#pragma unroll
                    for (int nf = 0; nf < 8; nf++) {
                        int col = wn * 64 + nf * 8 + qcol * 2;
                        float2 v;
                        v.x = acc[mf][nf][half * 2 + 0] + brow[col + 0];
                        v.y = acc[mf][nf][half * 2 + 1] + brow[col + 1];
                        *(float2*)(orow + col) = v;
                    }
                } else {
                    float sc = g_wslot[ent];
                    float* orow = g_ybuf + (size_t)ent * DDIM + n0;
#pragma unroll
                    for (int nf = 0; nf < 8; nf++) {
                        int col = wn * 64 + nf * 8 + qcol * 2;
                        float2 v;
                        v.x = (acc[mf][nf][half * 2 + 0] + brow[col + 0]) * sc;
                        v.y = (acc[mf][nf][half * 2 + 1] + brow[col + 1]) * sc;
                        *(float2*)(orow + col) = v;
                    }
                }
            }
        }
        __syncthreads();   // protect s_entry before next item overwrites it
    }
}

// ---------------- exact GELU + LayerNorm (fp32 in, fp16 out) ----------------
__global__ __launch_bounds__(256) void gelu_ln_kernel()
{
    const float* ln_w = g_p[IX_LNW];
    const float* ln_b = g_p[IX_LNB];

    int slot = blockIdx.x;
    int e = g_eslot[slot];
    const float* h = g_hbuf + (size_t)slot * HDIM;
    __half* ho = g_hh + (size_t)slot * HDIM;
    const int PER = HDIM / 256;

    float vals[PER];
    float s = 0.f, s2 = 0.f;
#pragma unroll
    for (int i = 0; i < PER; i++) {
        int j = threadIdx.x + i * 256;
        float v = h[j];
        v = 0.5f * v * (1.0f + erff(v * 0.70710678118654752f));
        vals[i] = v;
        s += v; s2 += v * v;
    }
#pragma unroll
    for (int off = 16; off; off >>= 1) {
        s  += __shfl_xor_sync(0xffffffffu, s,  off);
        s2 += __shfl_xor_sync(0xffffffffu, s2, off);
    }
    __shared__ float shs[8], shs2[8];
    __shared__ float sh_mean, sh_inv;
    int wid = threadIdx.x >> 5, lane = threadIdx.x & 31;
    if (lane == 0) { shs[wid] = s; shs2[wid] = s2; }
    __syncthreads();
    if (threadIdx.x == 0) {
        float ts = 0.f, ts2 = 0.f;
#pragma unroll
        for (int w = 0; w < 8; w++) { ts += shs[w]; ts2 += shs2[w]; }
        float mean = ts * (1.0f / HDIM);
        float var  = ts2 * (1.0f / HDIM) - mean * mean;
        sh_mean = mean;
        sh_inv  = rsqrtf(var + LN_EPS);
    }
    __syncthreads();
    float mean = sh_mean, inv = sh_inv;
    const float* lw = ln_w + (size_t)e * HDIM;
    const float* lb = ln_b + (size_t)e * HDIM;
#pragma unroll
    for (int i = 0; i < PER; i++) {
        int j = threadIdx.x + i * 256;
        float o = (vals[i] - mean) * inv * lw[j] + lb[j];
        ho[j] = __float2half_rn(o);
    }
}

// ---------------- combine: out[t] = sum over the token's 4 slots ------------
__global__ __launch_bounds__(256) void combine_kernel(float* __restrict__ out)
{
    int i = blockIdx.x * blockDim.x + threadIdx.x;
    if (i >= T_TOK * (DDIM / 4)) return;
    int t = i / (DDIM / 4);
    int j = (i % (DDIM / 4)) * 4;
    const float* yb = g_ybuf + ((size_t)t * NSLOT) * DDIM + j;
    float4 a = *(const float4*)(yb + 0 * DDIM);
    float4 b = *(const float4*)(yb + 1 * DDIM);
    float4 c = *(const float4*)(yb + 2 * DDIM);
    float4 d = *(const float4*)(yb + 3 * DDIM);
    float4 r;
    r.x = a.x + b.x + c.x + d.x;
    r.y = a.y + b.y + c.y + d.y;
    r.z = a.z + b.z + c.z + d.z;
    r.w = a.w + b.w + c.w + d.w;
    *(float4*)(out + (size_t)t * DDIM + j) = r;
}

// ---------------- launch ----------------
extern "C" void kernel_launch(void* const* d_in, const int* in_sizes, int n_in,
                              void* d_out, int out_size)
{
    InArgs a;
    int n = n_in < 9 ? n_in : 9;
    for (int i = 0; i < 9; i++) {
        a.p[i]  = (i < n) ? (const float*)d_in[i] : (const float*)d_in[n - 1];
        a.sz[i] = (i < n) ? in_sizes[i] : 0;
    }
    a.n = n;
    float* out = (float*)d_out;

    cudaFuncSetAttribute(expert_gemm_fp16,
                         cudaFuncAttributeMaxDynamicSharedMemorySize, GEMM_SMEM);

    classify_kernel<<<1, 32>>>(a);
    gate_kernel<<<(T_TOK * 32) / 256, 256>>>();
    cvt_all_kernel<<<(2 * WQUARTS + XQUARTS + 255) / 256, 256>>>();

    expert_gemm_fp16<<<NPERSIST, 256, GEMM_SMEM>>>(0);
    gelu_ln_kernel<<<TOTSLOT, 256>>>();
    expert_gemm_fp16<<<NPERSIST, 256, GEMM_SMEM>>>(1);
    combine_kernel<<<(T_TOK * (DDIM / 4) + 255) / 256, 256>>>(out);
}

// round 11
// speedup vs baseline: 1.0200x; 1.0200x over previous
#include <cuda_runtime.h>
#include <cuda_fp16.h>
#include <math.h>
#include <stdint.h>

// ---------------- problem constants ----------------
#define T_TOK   2048
#define DDIM    768
#define HDIM    1536
#define NEXP    16
#define NSLOT   4
#define TOTSLOT (T_TOK*NSLOT)
#define LN_EPS  1e-5f

#define IX_X    0
#define IX_GW   1
#define IX_GB   2
#define IX_F1W  3
#define IX_F1B  4
#define IX_LNW  5
#define IX_LNB  6
#define IX_F2W  7
#define IX_F2B  8

// ---------------- device scratch ----------------
__device__ const float* g_p[9];
__device__ int   g_ecnt[NEXP];
__device__ int   g_elist[NEXP * T_TOK];
__device__ __align__(16) float  g_wslot[TOTSLOT];
__device__ int   g_eslot[TOTSLOT];
__device__ __align__(16) __half g_hh[(size_t)TOTSLOT * HDIM];            // fc1 out / LN out (fp16)
__device__ __align__(16) float  g_ybuf[(size_t)TOTSLOT * DDIM];          // fc2 out fp32
__device__ __align__(16) __half g_xh[(size_t)T_TOK * DDIM];              // x fp16
__device__ __align__(16) __half g_w1h[(size_t)NEXP * DDIM * HDIM];
__device__ __align__(16) __half g_w2h[(size_t)NEXP * HDIM * DDIM];

struct InArgs { const float* p[9]; int sz[9]; int n; };

// ---------------- classify inputs (warp-parallel value scans) ----------------
__global__ void classify_kernel(InArgs a) {
    int lane = threadIdx.x;
    if (lane < NEXP) g_ecnt[lane] = 0;

    __shared__ int nzf[9], onesf[9];
    for (int i = 0; i < 9; i++) {
        bool nz = false, ones = true;
        if (i < a.n) {
            for (int j = lane; j < 256; j += 32)
                if (a.p[i][j] != 0.f) { nz = true; break; }
            for (int j = lane; j < 64; j += 32)
                if (a.p[i][j] != 1.0f) { ones = false; break; }
        }
        unsigned nzb = __ballot_sync(0xffffffffu, nz);
        unsigned onb = __ballot_sync(0xffffffffu, !ones);
        if (lane == 0) { nzf[i] = (nzb != 0); onesf[i] = (onb == 0); }
    }
    __syncwarp();
    if (lane != 0) return;

    bool used[9]; const float* P[9];
#pragma unroll
    for (int i = 0; i < 9; i++) { used[i] = false; P[i] = nullptr; }

    for (int i = 0; i < a.n && i < 9; i++) {
        if (a.sz[i] == T_TOK * DDIM)      { P[IX_X]  = a.p[i]; used[i] = true; }
        else if (a.sz[i] == NEXP)         { P[IX_GB] = a.p[i]; used[i] = true; }
    }
    for (int i = 0; i < a.n && i < 9; i++) {
        if (!used[i] && a.sz[i] == NEXP * DDIM * HDIM) {
            if (!P[IX_F1W]) P[IX_F1W] = a.p[i]; else P[IX_F2W] = a.p[i];
            used[i] = true;
        }
    }
    for (int i = 0; i < a.n && i < 9; i++) {
        if (!used[i] && a.sz[i] == DDIM * NEXP) {
            if (nzf[i] && !P[IX_GW]) P[IX_GW] = a.p[i];
            else if (!P[IX_F2B])     P[IX_F2B] = a.p[i];
            else                     P[IX_GW]  = a.p[i];
            used[i] = true;
        }
    }
    for (int i = 0; i < a.n && i < 9; i++) {
        if (!used[i] && a.sz[i] == NEXP * HDIM) {
            if (onesf[i] && !P[IX_LNW]) P[IX_LNW] = a.p[i];
            else if (!P[IX_F1B])        P[IX_F1B] = a.p[i];
            else if (!P[IX_LNB])        P[IX_LNB] = a.p[i];
            else                        P[IX_LNW] = a.p[i];
            used[i] = true;
        }
    }
#pragma unroll
    for (int k = 0; k < 9; k++) if (!P[k]) P[k] = a.p[k];
#pragma unroll
    for (int k = 0; k < 9; k++) g_p[k] = P[k];
}

// ---------------- gating: one warp per token (full fp32) ----------------
__global__ __launch_bounds__(256) void gate_kernel()
{
    const float* x  = g_p[IX_X];
    const float* gw = g_p[IX_GW];
    const float* gb = g_p[IX_GB];

    int gtid = blockIdx.x * blockDim.x + threadIdx.x;
    int t    = gtid >> 5;
    int lane = gtid & 31;
    if (t >= T_TOK) return;

    float acc[NEXP];
#pragma unroll
    for (int e = 0; e < NEXP; e++) acc[e] = 0.f;

    const float* xr = x + (size_t)t * DDIM;
    for (int d = lane; d < DDIM; d += 32) {
        float xv = xr[d];
        const float* wr = gw + d * NEXP;
#pragma unroll
        for (int e = 0; e < NEXP; e++) acc[e] += xv * wr[e];
    }
#pragma unroll
    for (int e = 0; e < NEXP; e++) {
#pragma unroll
        for (int off = 16; off; off >>= 1)
            acc[e] += __shfl_xor_sync(0xffffffffu, acc[e], off);
    }

    if (lane == 0) {
        float s[NEXP];
#pragma unroll
        for (int e = 0; e < NEXP; e++) s[e] = acc[e] + gb[e];
        s[0] = -1e9f;
        float mx = s[0];
#pragma unroll
        for (int e = 1; e < NEXP; e++) mx = fmaxf(mx, s[e]);
        float p[NEXP]; float sum = 0.f;
#pragma unroll
        for (int e = 0; e < NEXP; e++) { p[e] = expf(s[e] - mx); sum += p[e]; }
        float inv = 1.f / sum;
#pragma unroll
        for (int e = 0; e < NEXP; e++) p[e] *= inv;

        int base = t * NSLOT;
        g_wslot[base] = 1.0f;
        g_eslot[base] = 0;
        int pos = atomicAdd(&g_ecnt[0], 1);
        g_elist[0 * T_TOK + pos] = base;

        for (int k = 0; k < 3; k++) {
            int bi = -1; float bv = -1.f;
#pragma unroll
            for (int e = 0; e < NEXP; e++)
                if (p[e] > bv) { bv = p[e]; bi = e; }
            p[bi] = -2.f;
            g_wslot[base + 1 + k] = bv;
            g_eslot[base + 1 + k] = bi;
            int pp = atomicAdd(&g_ecnt[bi], 1);
            g_elist[bi * T_TOK + pp] = base + 1 + k;
        }
    }
}

// ---------------- convert weights + x to fp16 (fused, streaming reads) -------
__device__ __forceinline__ uint2 f4_to_h4(float4 v) {
    __half2 lo = __floats2half2_rn(v.x, v.y);
    __half2 hi = __floats2half2_rn(v.z, v.w);
    return make_uint2(*(uint32_t*)&lo, *(uint32_t*)&hi);
}
#define WQUARTS (NEXP * DDIM * HDIM / 4)
#define XQUARTS (T_TOK * DDIM / 4)
__global__ __launch_bounds__(256) void cvt_all_kernel()
{
    int i = blockIdx.x * blockDim.x + threadIdx.x;
    if (i < WQUARTS) {
        float4 v = __ldcs((const float4*)g_p[IX_F1W] + i);
        ((uint2*)g_w1h)[i] = f4_to_h4(v);
    } else if (i < 2 * WQUARTS) {
        int j = i - WQUARTS;
        float4 v = __ldcs((const float4*)g_p[IX_F2W] + j);
        ((uint2*)g_w2h)[j] = f4_to_h4(v);
    } else if (i < 2 * WQUARTS + XQUARTS) {
        int j = i - 2 * WQUARTS;
        float4 v = ((const float4*)g_p[IX_X])[j];
        ((uint2*)g_xh)[j] = f4_to_h4(v);
    }
}

// ---------------- fp16 MMA helpers ----------------
__device__ __forceinline__ void ldsm_x4(uint32_t& r0, uint32_t& r1, uint32_t& r2, uint32_t& r3,
                                        uint32_t addr) {
    asm volatile("ldmatrix.sync.aligned.m8n8.x4.shared.b16 {%0,%1,%2,%3}, [%4];"
                 : "=r"(r0), "=r"(r1), "=r"(r2), "=r"(r3) : "r"(addr));
}
__device__ __forceinline__ void ldsm_x4t(uint32_t& r0, uint32_t& r1, uint32_t& r2, uint32_t& r3,
                                         uint32_t addr) {
    asm volatile("ldmatrix.sync.aligned.m8n8.x4.trans.shared.b16 {%0,%1,%2,%3}, [%4];"
                 : "=r"(r0), "=r"(r1), "=r"(r2), "=r"(r3) : "r"(addr));
}
__device__ __forceinline__ void mma_f16(float c[4],
    uint32_t a0, uint32_t a1, uint32_t a2, uint32_t a3,
    uint32_t b0, uint32_t b1)
{
    asm volatile(
        "mma.sync.aligned.m16n8k16.row.col.f32.f16.f16.f32 "
        "{%0,%1,%2,%3}, {%4,%5,%6,%7}, {%8,%9}, {%0,%1,%2,%3};"
        : "+f"(c[0]), "+f"(c[1]), "+f"(c[2]), "+f"(c[3])
        : "r"(a0), "r"(a1), "r"(a2), "r"(a3), "r"(b0), "r"(b1));
}
__device__ __forceinline__ void cp16(uint32_t dst, const void* src) {
    asm volatile("cp.async.ca.shared.global [%0], [%1], 16;\n" :: "r"(dst), "l"(src));
}
#define CP_COMMIT() asm volatile("cp.async.commit_group;\n" ::: "memory")
#define CP_WAIT0()  asm volatile("cp.async.wait_group 0;\n" ::: "memory")
#define CP_WAIT1()  asm volatile("cp.async.wait_group 1;\n" ::: "memory")

// ---------------- gathered expert GEMM (templated on layer) -----------------
// BM=128, BK=64, 3-stage cp.async, 8 warps (2m x 4n).
// WHICH=0 (fc1): BN=256, warp tile 64x64, out = g_hh (fp16, +bias)
// WHICH=1 (fc2): BN=128, warp tile 64x32, out = g_ybuf (fp32, (+bias)*scale)
#define BM 128
#define BK 64
#define MT 16
#define AST 72
#define A_STG (BM * AST)                 // 9216 halfs
#define NSTG 3

template <int WHICH>
__global__ __launch_bounds__(256, 1) void expert_gemm(int mtiles_per_e)
{
    constexpr int KD    = WHICH ? HDIM : DDIM;
    constexpr int ND    = WHICH ? DDIM : HDIM;
    constexpr int BNW   = WHICH ? 128 : 256;
    constexpr int BSTW  = BNW + 8;            // B row stride (halfs)
    constexpr int B_STG = BK * BSTW;
    constexpr int STG_H = A_STG + B_STG;
    constexpr int WNT   = BNW / 4;            // warp tile N: 64 / 32
    constexpr int NF    = WNT / 8;            // 8 / 4
    constexpr int NG    = WNT / 16;           // 4 / 2
    constexpr int CPR   = BNW / 8;            // B chunks per row: 32 / 16
    constexpr int RPP   = 256 / CPR;          // B rows per pass: 8 / 16
    constexpr int QB    = BK / RPP;           // B passes: 8 / 4

    extern __shared__ __half smh[];
    int* s_entry = (int*)(smh + NSTG * STG_H);

    const __half* Asrc = WHICH ? g_hh : g_xh;
    const __half* W    = WHICH ? g_w2h : g_w1h;
    const float*  bias = g_p[WHICH ? IX_F2B : IX_F1B];

    int e  = blockIdx.x / mtiles_per_e;
    int mt = blockIdx.x % mtiles_per_e;
    int cnt = g_ecnt[e];
    int m0 = mt * BM;
    if (m0 >= cnt) return;
    int n0 = blockIdx.y * BNW;

    int tid  = threadIdx.x;
    int lane = tid & 31;
    int wid  = tid >> 5;
    int wm   = wid >> 2;     // 0..1 -> 64 rows
    int wn   = wid & 3;      // 0..3 -> WNT cols

    if (tid < BM) {
        int gm = m0 + tid;
        s_entry[tid] = (gm < cnt) ? g_elist[e * T_TOK + gm] : -1;
    }
    __syncthreads();

    // ---- cp.async mappings ----
    int a_rb = tid >> 3;
    int a_j  = (tid & 7) * 8;
    const __half* aptr[4];
    uint32_t aDst[4];
#pragma unroll
    for (int q = 0; q < 4; q++) {
        int row = a_rb + 32 * q;
        int ent = s_entry[row];
        int ar  = (ent >= 0) ? (WHICH ? ent : (ent >> 2)) : 0;
        aptr[q] = Asrc + (size_t)ar * KD + a_j;
        aDst[q] = (uint32_t)(row * AST + a_j) * 2;
    }
    int b_rb = tid / CPR;
    int b_j  = (tid % CPR) * 8;
    const __half* wrow = W + (size_t)e * KD * ND + n0 + b_j;
    uint32_t bDst[QB];
#pragma unroll
    for (int q = 0; q < QB; q++)
        bDst[q] = (uint32_t)(A_STG + (b_rb + RPP * q) * BSTW + b_j) * 2;

    uint32_t sbase = (uint32_t)__cvta_generic_to_shared(smh);

    float acc[4][NF][4];
#pragma unroll
    for (int i = 0; i < 4; i++)
#pragma unroll
        for (int j = 0; j < NF; j++)
#pragma unroll
            for (int q = 0; q < 4; q++) acc[i][j][q] = 0.f;

    int lr = lane & 15;
    int lc = lane >> 4;
    uint32_t aOff[4];
#pragma unroll
    for (int mf = 0; mf < 4; mf++)
        aOff[mf] = (uint32_t)(((wm * 64 + mf * 16 + lr) * AST + lc * 8) * 2);
    uint32_t bOff = (uint32_t)((A_STG + lr * BSTW + wn * WNT + lc * 8) * 2);

    constexpr int nk = KD / BK;   // 12 / 24

    // prologue: tiles 0, 1
#pragma unroll
    for (int s = 0; s < NSTG - 1; s++) {
        uint32_t st = sbase + (uint32_t)(s * STG_H * 2);
        int k0 = s * BK;
#pragma unroll
        for (int q = 0; q < 4; q++) cp16(st + aDst[q], aptr[q] + k0);
#pragma unroll
        for (int q = 0; q < QB; q++)
            cp16(st + bDst[q], wrow + (size_t)(k0 + b_rb + RPP * q) * ND);
        CP_COMMIT();
    }

    for (int kt = 0; kt < nk; kt++) {
        if (kt + 1 < nk) { CP_WAIT1(); } else { CP_WAIT0(); }
        __syncthreads();

        int nxt = kt + NSTG - 1;
        if (nxt < nk) {
            uint32_t st = sbase + (uint32_t)((nxt % NSTG) * STG_H * 2);
            int k0 = nxt * BK;
#pragma unroll
            for (int q = 0; q < 4; q++) cp16(st + aDst[q], aptr[q] + k0);
#pragma unroll
            for (int q = 0; q < QB; q++)
                cp16(st + bDst[q], wrow + (size_t)(k0 + b_rb + RPP * q) * ND);
            CP_COMMIT();
        }

        uint32_t stg = sbase + (uint32_t)((kt % NSTG) * STG_H * 2);

        // register-double-buffered ldmatrix over 4 k-steps of 16
        uint32_t af[2][4][4], bf[2][NG][4];
#pragma unroll
        for (int mf = 0; mf < 4; mf++)
            ldsm_x4(af[0][mf][0], af[0][mf][1], af[0][mf][2], af[0][mf][3],
                    stg + aOff[mf]);
#pragma unroll
        for (int ng = 0; ng < NG; ng++)
            ldsm_x4t(bf[0][ng][0], bf[0][ng][1], bf[0][ng][2], bf[0][ng][3],
                     stg + bOff + (uint32_t)(ng * 32));

#pragma unroll
        for (int ks = 0; ks < 4; ks++) {
            int cb = ks & 1;
            if (ks < 3) {
                int nb = cb ^ 1;
                uint32_t ka = (uint32_t)((ks + 1) * 32);
                uint32_t kb = (uint32_t)((ks + 1) * 16 * BSTW * 2);
#pragma unroll
                for (int mf = 0; mf < 4; mf++)
                    ldsm_x4(af[nb][mf][0], af[nb][mf][1], af[nb][mf][2], af[nb][mf][3],
                            stg + aOff[mf] + ka);
#pragma unroll
                for (int ng = 0; ng < NG; ng++)
                    ldsm_x4t(bf[nb][ng][0], bf[nb][ng][1], bf[nb][ng][2], bf[nb][ng][3],
                             stg + bOff + kb + (uint32_t)(ng * 32));
            }
#pragma unroll
            for (int mf = 0; mf < 4; mf++)
#pragma unroll
                for (int nf = 0; nf < NF; nf++) {
                    int ng = nf >> 1, hh = (nf & 1) * 2;
                    mma_f16(acc[mf][nf],
                            af[cb][mf][0], af[cb][mf][1], af[cb][mf][2], af[cb][mf][3],
                            bf[cb][ng][hh], bf[cb][ng][hh + 1]);
                }
        }
    }

    // ---- epilogue ----
    int qrow = lane >> 2;
    int qcol = lane & 3;
    const float* brow = bias + (size_t)e * ND + n0;
#pragma unroll
    for (int mf = 0; mf < 4; mf++) {
        int r0 = wm * 64 + mf * 16 + qrow;
#pragma unroll
        for (int half = 0; half < 2; half++) {
            int r = r0 + half * 8;
            int ent = s_entry[r];
            if (ent < 0) continue;
            if (WHICH == 0) {
                __half* orow = g_hh + (size_t)ent * HDIM + n0;
#pragma unroll
                for (int nf = 0; nf < NF; nf++) {
                    int col = wn * WNT + nf * 8 + qcol * 2;
                    float vx = acc[mf][nf][half * 2 + 0] + brow[col + 0];
                    float vy = acc[mf][nf][half * 2 + 1] + brow[col + 1];
                    *(__half2*)(orow + col) = __floats2half2_rn(vx, vy);
                }
            } else {
                float sc = g_wslot[ent];
                float* orow = g_ybuf + (size_t)ent * DDIM + n0;
#pragma unroll
                for (int nf = 0; nf < NF; nf++) {
                    int col = wn * WNT + nf * 8 + qcol * 2;
                    float2 v;
                    v.x = (acc[mf][nf][half * 2 + 0] + brow[col + 0]) * sc;
                    v.y = (acc[mf][nf][half * 2 + 1] + brow[col + 1]) * sc;
                    *(float2*)(orow + col) = v;
                }
            }
        }
    }
}

#define SMEM0 (NSTG * (A_STG + BK * 264) * 2 + BM * 4)
#define SMEM1 (NSTG * (A_STG + BK * 136) * 2 + BM * 4)

// ---------------- exact GELU + LayerNorm (fp16 in, fp16 out, in place) ------
__global__ __launch_bounds__(256) void gelu_ln_kernel()
{
    const float* ln_w = g_p[IX_LNW];
    const float* ln_b = g_p[IX_LNB];

    int slot = blockIdx.x;
    int e = g_eslot[slot];
    __half* h = g_hh + (size_t)slot * HDIM;
    const int PER = HDIM / 256;

    float vals[PER];
    float s = 0.f, s2 = 0.f;
#pragma unroll
    for (int i = 0; i < PER; i++) {
        int j = threadIdx.x + i * 256;
        float v = __half2float(h[j]);
        v = 0.5f * v * (1.0f + erff(v * 0.70710678118654752f));
        vals[i] = v;
        s += v; s2 += v * v;
    }
#pragma unroll
    for (int off = 16; off; off >>= 1) {
        s  += __shfl_xor_sync(0xffffffffu, s,  off);
        s2 += __shfl_xor_sync(0xffffffffu, s2, off);
    }
    __shared__ float shs[8], shs2[8];
    __shared__ float sh_mean, sh_inv;
    int wid = threadIdx.x >> 5, lane = threadIdx.x & 31;
    if (lane == 0) { shs[wid] = s; shs2[wid] = s2; }
    __syncthreads();
    if (threadIdx.x == 0) {
        float ts = 0.f, ts2 = 0.f;
#pragma unroll
        for (int w = 0; w < 8; w++) { ts += shs[w]; ts2 += shs2[w]; }
        float mean = ts * (1.0f / HDIM);
        float var  = ts2 * (1.0f / HDIM) - mean * mean;
        sh_mean = mean;
        sh_inv  = rsqrtf(var + LN_EPS);
    }
    __syncthreads();
    float mean = sh_mean, inv = sh_inv;
    const float* lw = ln_w + (size_t)e * HDIM;
    const float* lb = ln_b + (size_t)e * HDIM;
#pragma unroll
    for (int i = 0; i < PER; i++) {
        int j = threadIdx.x + i * 256;
        float o = (vals[i] - mean) * inv * lw[j] + lb[j];
        h[j] = __float2half_rn(o);
    }
}

// ---------------- combine: out[t] = sum over the token's 4 slots ------------
__global__ __launch_bounds__(256) void combine_kernel(float* __restrict__ out)
{
    int i = blockIdx.x * blockDim.x + threadIdx.x;
    if (i >= T_TOK * (DDIM / 4)) return;
    int t = i / (DDIM / 4);
    int j = (i % (DDIM / 4)) * 4;
    const float* yb = g_ybuf + ((size_t)t * NSLOT) * DDIM + j;
    float4 a = *(const float4*)(yb + 0 * DDIM);
    float4 b = *(const float4*)(yb + 1 * DDIM);
    float4 c = *(const float4*)(yb + 2 * DDIM);
    float4 d = *(const float4*)(yb + 3 * DDIM);
    float4 r;
    r.x = a.x + b.x + c.x + d.x;
    r.y = a.y + b.y + c.y + d.y;
    r.z = a.z + b.z + c.z + d.z;
    r.w = a.w + b.w + c.w + d.w;
    *(float4*)(out + (size_t)t * DDIM + j) = r;
}

// ---------------- launch ----------------
extern "C" void kernel_launch(void* const* d_in, const int* in_sizes, int n_in,
                              void* d_out, int out_size)
{
    InArgs a;
    int n = n_in < 9 ? n_in : 9;
    for (int i = 0; i < 9; i++) {
        a.p[i]  = (i < n) ? (const float*)d_in[i] : (const float*)d_in[n - 1];
        a.sz[i] = (i < n) ? in_sizes[i] : 0;
    }
    a.n = n;
    float* out = (float*)d_out;

    cudaFuncSetAttribute(expert_gemm<0>,
                         cudaFuncAttributeMaxDynamicSharedMemorySize, SMEM0);
    cudaFuncSetAttribute(expert_gemm<1>,
                         cudaFuncAttributeMaxDynamicSharedMemorySize, SMEM1);

    classify_kernel<<<1, 32>>>(a);
    gate_kernel<<<(T_TOK * 32) / 256, 256>>>();
    cvt_all_kernel<<<(2 * WQUARTS + XQUARTS + 255) / 256, 256>>>();

    expert_gemm<0><<<dim3(NEXP * MT, HDIM / 256), 256, SMEM0>>>(MT);
    gelu_ln_kernel<<<TOTSLOT, 256>>>();
    expert_gemm<1><<<dim3(NEXP * MT, DDIM / 128), 256, SMEM1>>>(MT);
    combine_kernel<<<(T_TOK * (DDIM / 4) + 255) / 256, 256>>>(out);
}

// round 12
// speedup vs baseline: 1.0722x; 1.0512x over previous
#include <cuda_runtime.h>
#include <cuda_fp16.h>
#include <math.h>
#include <stdint.h>

// ---------------- problem constants ----------------
#define T_TOK   2048
#define DDIM    768
#define HDIM    1536
#define NEXP    16
#define NSLOT   4
#define TOTSLOT (T_TOK*NSLOT)
#define LN_EPS  1e-5f

#define IX_X    0
#define IX_GW   1
#define IX_GB   2
#define IX_F1W  3
#define IX_F1B  4
#define IX_LNW  5
#define IX_LNB  6
#define IX_F2W  7
#define IX_F2B  8

// ---------------- device scratch ----------------
__device__ const float* g_p[9];
__device__ int   g_ecnt[NEXP];
__device__ int   g_elist[NEXP * T_TOK];
__device__ __align__(16) float  g_wslot[TOTSLOT];
__device__ int   g_eslot[TOTSLOT];
__device__ __align__(16) __half g_hh[(size_t)TOTSLOT * HDIM];            // fc1 out / LN out (fp16)
__device__ __align__(16) float  g_ybuf[(size_t)TOTSLOT * DDIM];          // fc2 out fp32
__device__ __align__(16) __half g_xh[(size_t)T_TOK * DDIM];              // x fp16
__device__ __align__(16) __half g_w1h[(size_t)NEXP * DDIM * HDIM];
__device__ __align__(16) __half g_w2h[(size_t)NEXP * HDIM * DDIM];

struct InArgs { const float* p[9]; int sz[9]; int n; };

// ---------------- classify inputs (warp-parallel value scans) ----------------
__global__ void classify_kernel(InArgs a) {
    int lane = threadIdx.x;
    if (lane < NEXP) g_ecnt[lane] = 0;

    __shared__ int nzf[9], onesf[9];
    for (int i = 0; i < 9; i++) {
        bool nz = false, ones = true;
        if (i < a.n) {
            for (int j = lane; j < 256; j += 32)
                if (a.p[i][j] != 0.f) { nz = true; break; }
            for (int j = lane; j < 64; j += 32)
                if (a.p[i][j] != 1.0f) { ones = false; break; }
        }
        unsigned nzb = __ballot_sync(0xffffffffu, nz);
        unsigned onb = __ballot_sync(0xffffffffu, !ones);
        if (lane == 0) { nzf[i] = (nzb != 0); onesf[i] = (onb == 0); }
    }
    __syncwarp();
    if (lane != 0) return;

    bool used[9]; const float* P[9];
#pragma unroll
    for (int i = 0; i < 9; i++) { used[i] = false; P[i] = nullptr; }

    for (int i = 0; i < a.n && i < 9; i++) {
        if (a.sz[i] == T_TOK * DDIM)      { P[IX_X]  = a.p[i]; used[i] = true; }
        else if (a.sz[i] == NEXP)         { P[IX_GB] = a.p[i]; used[i] = true; }
    }
    for (int i = 0; i < a.n && i < 9; i++) {
        if (!used[i] && a.sz[i] == NEXP * DDIM * HDIM) {
            if (!P[IX_F1W]) P[IX_F1W] = a.p[i]; else P[IX_F2W] = a.p[i];
            used[i] = true;
        }
    }
    for (int i = 0; i < a.n && i < 9; i++) {
        if (!used[i] && a.sz[i] == DDIM * NEXP) {
            if (nzf[i] && !P[IX_GW]) P[IX_GW] = a.p[i];
            else if (!P[IX_F2B])     P[IX_F2B] = a.p[i];
            else                     P[IX_GW]  = a.p[i];
            used[i] = true;
        }
    }
    for (int i = 0; i < a.n && i < 9; i++) {
        if (!used[i] && a.sz[i] == NEXP * HDIM) {
            if (onesf[i] && !P[IX_LNW]) P[IX_LNW] = a.p[i];
            else if (!P[IX_F1B])        P[IX_F1B] = a.p[i];
            else if (!P[IX_LNB])        P[IX_LNB] = a.p[i];
            else                        P[IX_LNW] = a.p[i];
            used[i] = true;
        }
    }
#pragma unroll
    for (int k = 0; k < 9; k++) if (!P[k]) P[k] = a.p[k];
#pragma unroll
    for (int k = 0; k < 9; k++) g_p[k] = P[k];
}

// ---------------- gating: one warp per token (full fp32) ----------------
__global__ __launch_bounds__(256) void gate_kernel()
{
    const float* x  = g_p[IX_X];
    const float* gw = g_p[IX_GW];
    const float* gb = g_p[IX_GB];

    int gtid = blockIdx.x * blockDim.x + threadIdx.x;
    int t    = gtid >> 5;
    int lane = gtid & 31;
    if (t >= T_TOK) return;

    float acc[NEXP];
#pragma unroll
    for (int e = 0; e < NEXP; e++) acc[e] = 0.f;

    const float* xr = x + (size_t)t * DDIM;
    for (int d = lane; d < DDIM; d += 32) {
        float xv = xr[d];
        const float* wr = gw + d * NEXP;
#pragma unroll
        for (int e = 0; e < NEXP; e++) acc[e] += xv * wr[e];
    }
#pragma unroll
    for (int e = 0; e < NEXP; e++) {
#pragma unroll
        for (int off = 16; off; off >>= 1)
            acc[e] += __shfl_xor_sync(0xffffffffu, acc[e], off);
    }

    if (lane == 0) {
        float s[NEXP];
#pragma unroll
        for (int e = 0; e < NEXP; e++) s[e] = acc[e] + gb[e];
        s[0] = -1e9f;
        float mx = s[0];
#pragma unroll
        for (int e = 1; e < NEXP; e++) mx = fmaxf(mx, s[e]);
        float p[NEXP]; float sum = 0.f;
#pragma unroll
        for (int e = 0; e < NEXP; e++) { p[e] = expf(s[e] - mx); sum += p[e]; }
        float inv = 1.f / sum;
#pragma unroll
        for (int e = 0; e < NEXP; e++) p[e] *= inv;

        int base = t * NSLOT;
        g_wslot[base] = 1.0f;
        g_eslot[base] = 0;
        int pos = atomicAdd(&g_ecnt[0], 1);
        g_elist[0 * T_TOK + pos] = base;

        for (int k = 0; k < 3; k++) {
            int bi = -1; float bv = -1.f;
#pragma unroll
            for (int e = 0; e < NEXP; e++)
                if (p[e] > bv) { bv = p[e]; bi = e; }
            p[bi] = -2.f;
            g_wslot[base + 1 + k] = bv;
            g_eslot[base + 1 + k] = bi;
            int pp = atomicAdd(&g_ecnt[bi], 1);
            g_elist[bi * T_TOK + pp] = base + 1 + k;
        }
    }
}

// ---------------- convert weights + x to fp16 ----------------
__device__ __forceinline__ uint2 f4_to_h4(float4 v) {
    __half2 lo = __floats2half2_rn(v.x, v.y);
    __half2 hi = __floats2half2_rn(v.z, v.w);
    return make_uint2(*(uint32_t*)&lo, *(uint32_t*)&hi);
}
#define WQUARTS (NEXP * DDIM * HDIM / 4)
#define XQUARTS (T_TOK * DDIM / 4)
__global__ __launch_bounds__(256) void cvt_all_kernel()
{
    int i = blockIdx.x * blockDim.x + threadIdx.x;
    if (i < WQUARTS) {
        float4 v = __ldcs((const float4*)g_p[IX_F1W] + i);
        ((uint2*)g_w1h)[i] = f4_to_h4(v);
    } else if (i < 2 * WQUARTS) {
        int j = i - WQUARTS;
        float4 v = __ldcs((const float4*)g_p[IX_F2W] + j);
        ((uint2*)g_w2h)[j] = f4_to_h4(v);
    } else if (i < 2 * WQUARTS + XQUARTS) {
        int j = i - 2 * WQUARTS;
        float4 v = ((const float4*)g_p[IX_X])[j];
        ((uint2*)g_xh)[j] = f4_to_h4(v);
    }
}

// ---------------- fp16 MMA helpers ----------------
__device__ __forceinline__ void ldsm_x4(uint32_t& r0, uint32_t& r1, uint32_t& r2, uint32_t& r3,
                                        uint32_t addr) {
    asm volatile("ldmatrix.sync.aligned.m8n8.x4.shared.b16 {%0,%1,%2,%3}, [%4];"
                 : "=r"(r0), "=r"(r1), "=r"(r2), "=r"(r3) : "r"(addr));
}
__device__ __forceinline__ void ldsm_x4t(uint32_t& r0, uint32_t& r1, uint32_t& r2, uint32_t& r3,
                                         uint32_t addr) {
    asm volatile("ldmatrix.sync.aligned.m8n8.x4.trans.shared.b16 {%0,%1,%2,%3}, [%4];"
                 : "=r"(r0), "=r"(r1), "=r"(r2), "=r"(r3) : "r"(addr));
}
__device__ __forceinline__ void mma_f16(float c[4],
    uint32_t a0, uint32_t a1, uint32_t a2, uint32_t a3,
    uint32_t b0, uint32_t b1)
{
    asm volatile(
        "mma.sync.aligned.m16n8k16.row.col.f32.f16.f16.f32 "
        "{%0,%1,%2,%3}, {%4,%5,%6,%7}, {%8,%9}, {%0,%1,%2,%3};"
        : "+f"(c[0]), "+f"(c[1]), "+f"(c[2]), "+f"(c[3])
        : "r"(a0), "r"(a1), "r"(a2), "r"(a3), "r"(b0), "r"(b1));
}
__device__ __forceinline__ void cp16(uint32_t dst, const void* src) {
    asm volatile("cp.async.ca.shared.global [%0], [%1], 16;\n" :: "r"(dst), "l"(src));
}
#define CP_COMMIT() asm volatile("cp.async.commit_group;\n" ::: "memory")
#define CP_WAIT2()  asm volatile("cp.async.wait_group 2;\n" ::: "memory")

// ---------------- gathered expert GEMM (fp16, occupancy-2) ------------------
// BM=128, BN=128, BK=32, 4-stage cp.async; 8 warps (2m x 4n), warp tile 64x32.
// acc = 64 regs/thread -> 2 CTAs/SM (16 warps) for tensor-pipe latency hiding.
#define BM 128
#define BN 128
#define BK 32
#define MT 16
#define AST 40                           // A row stride (halfs)
#define BST 136                          // B row stride (halfs)
#define NSTG 4
#define A_STG (BM * AST)                 // 5120 halfs
#define B_STG (BK * BST)                 // 4352 halfs
#define STG_H (A_STG + B_STG)            // 9472 halfs
#define GEMM_SMEM (NSTG * STG_H * 2 + BM * 4)   // ~76.3 KB

template <int WHICH>
__global__ __launch_bounds__(256, 2) void expert_gemm(int mtiles_per_e)
{
    constexpr int KD = WHICH ? HDIM : DDIM;
    constexpr int ND = WHICH ? DDIM : HDIM;

    extern __shared__ __half smh[];
    int* s_entry = (int*)(smh + NSTG * STG_H);

    const __half* Asrc = WHICH ? g_hh : g_xh;
    const __half* W    = WHICH ? g_w2h : g_w1h;
    const float*  bias = g_p[WHICH ? IX_F2B : IX_F1B];

    int e  = blockIdx.x / mtiles_per_e;
    int mt = blockIdx.x % mtiles_per_e;
    int cnt = g_ecnt[e];
    int m0 = mt * BM;
    if (m0 >= cnt) return;
    int n0 = blockIdx.y * BN;

    int tid  = threadIdx.x;
    int lane = tid & 31;
    int wid  = tid >> 5;
    int wm   = wid >> 2;     // 0..1 -> 64 rows
    int wn   = wid & 3;      // 0..3 -> 32 cols each

    if (tid < BM) {
        int gm = m0 + tid;
        s_entry[tid] = (gm < cnt) ? g_elist[e * T_TOK + gm] : -1;
    }
    __syncthreads();

    // ---- cp.async mappings (2 chunks A, 2 chunks B per thread) ----
    // A: 512 chunks: chunk c: row=c>>2, j=(c&3)*8; thread t -> c = t, t+256
    int a_row0 = tid >> 2;
    int a_row1 = a_row0 + 64;
    int a_j    = (tid & 3) * 8;
    int ent0 = s_entry[a_row0], ent1 = s_entry[a_row1];
    int ar0 = (ent0 >= 0) ? (WHICH ? ent0 : (ent0 >> 2)) : 0;
    int ar1 = (ent1 >= 0) ? (WHICH ? ent1 : (ent1 >> 2)) : 0;
    const __half* aptr0 = Asrc + (size_t)ar0 * KD + a_j;
    const __half* aptr1 = Asrc + (size_t)ar1 * KD + a_j;
    uint32_t aDst0 = (uint32_t)(a_row0 * AST + a_j) * 2;
    uint32_t aDst1 = (uint32_t)(a_row1 * AST + a_j) * 2;
    // B: 512 chunks: chunk c: row=c>>4, j=(c&15)*8; thread t -> c = t, t+256
    int b_row0 = tid >> 4;
    int b_row1 = b_row0 + 16;
    int b_j    = (tid & 15) * 8;
    const __half* wbase = W + (size_t)e * KD * ND + n0 + b_j;
    uint32_t bDst0 = (uint32_t)(A_STG + b_row0 * BST + b_j) * 2;
    uint32_t bDst1 = (uint32_t)(A_STG + b_row1 * BST + b_j) * 2;

    uint32_t sbase = (uint32_t)__cvta_generic_to_shared(smh);

    float acc[4][4][4];
#pragma unroll
    for (int i = 0; i < 4; i++)
#pragma unroll
        for (int j = 0; j < 4; j++)
#pragma unroll
            for (int q = 0; q < 4; q++) acc[i][j][q] = 0.f;

    int lr = lane & 15;
    int lc = lane >> 4;
    uint32_t aOff[4];
#pragma unroll
    for (int mf = 0; mf < 4; mf++)
        aOff[mf] = (uint32_t)(((wm * 64 + mf * 16 + lr) * AST + lc * 8) * 2);
    uint32_t bOff = (uint32_t)((A_STG + lr * BST + wn * 32 + lc * 8) * 2);

    constexpr int nk = KD / BK;   // 24 / 48

    // prologue: stages 0..2
#pragma unroll
    for (int s = 0; s < NSTG - 1; s++) {
        uint32_t st = sbase + (uint32_t)(s * STG_H * 2);
        int k0 = s * BK;
        cp16(st + aDst0, aptr0 + k0);
        cp16(st + aDst1, aptr1 + k0);
        cp16(st + bDst0, wbase + (size_t)(k0 + b_row0) * ND);
        cp16(st + bDst1, wbase + (size_t)(k0 + b_row1) * ND);
        CP_COMMIT();
    }

    for (int kt = 0; kt < nk; kt++) {
        CP_WAIT2();
        __syncthreads();

        int nxt = kt + NSTG - 1;
        if (nxt < nk) {
            uint32_t st = sbase + (uint32_t)((nxt % NSTG) * STG_H * 2);
            int k0 = nxt * BK;
            cp16(st + aDst0, aptr0 + k0);
            cp16(st + aDst1, aptr1 + k0);
            cp16(st + bDst0, wbase + (size_t)(k0 + b_row0) * ND);
            cp16(st + bDst1, wbase + (size_t)(k0 + b_row1) * ND);
        }
        CP_COMMIT();   // commit every iter (possibly empty) to keep group count uniform

        uint32_t stg = sbase + (uint32_t)((kt % NSTG) * STG_H * 2);

#pragma unroll
        for (int ks = 0; ks < 2; ks++) {
            uint32_t a[4][4];
#pragma unroll
            for (int mf = 0; mf < 4; mf++)
                ldsm_x4(a[mf][0], a[mf][1], a[mf][2], a[mf][3],
                        stg + aOff[mf] + ks * 32);
            uint32_t b[2][4];
#pragma unroll
            for (int ng = 0; ng < 2; ng++)
                ldsm_x4t(b[ng][0], b[ng][1], b[ng][2], b[ng][3],
                         stg + bOff + (uint32_t)(ks * 16 * BST * 2 + ng * 16 * 2));
#pragma unroll
            for (int mf = 0; mf < 4; mf++)
#pragma unroll
                for (int nf = 0; nf < 4; nf++) {
                    int ng = nf >> 1, hh = (nf & 1) * 2;
                    mma_f16(acc[mf][nf], a[mf][0], a[mf][1], a[mf][2], a[mf][3],
                            b[ng][hh], b[ng][hh + 1]);
                }
        }
    }

    // ---- epilogue ----
    int qrow = lane >> 2;
    int qcol = lane & 3;
    const float* brow = bias + (size_t)e * ND + n0;
#pragma unroll
    for (int mf = 0; mf < 4; mf++) {
        int r0 = wm * 64 + mf * 16 + qrow;
#pragma unroll
        for (int half = 0; half < 2; half++) {
            int r = r0 + half * 8;
            int ent = s_entry[r];
            if (ent < 0) continue;
            if (WHICH == 0) {
                __half* orow = g_hh + (size_t)ent * HDIM + n0;
#pragma unroll
                for (int nf = 0; nf < 4; nf++) {
                    int col = wn * 32 + nf * 8 + qcol * 2;
                    float vx = acc[mf][nf][half * 2 + 0] + brow[col + 0];
                    float vy = acc[mf][nf][half * 2 + 1] + brow[col + 1];
                    *(__half2*)(orow + col) = __floats2half2_rn(vx, vy);
                }
            } else {
                float sc = g_wslot[ent];
                float* orow = g_ybuf + (size_t)ent * DDIM + n0;
#pragma unroll
                for (int nf = 0; nf < 4; nf++) {
                    int col = wn * 32 + nf * 8 + qcol * 2;
                    float2 v;
                    v.x = (acc[mf][nf][half * 2 + 0] + brow[col + 0]) * sc;
                    v.y = (acc[mf][nf][half * 2 + 1] + brow[col + 1]) * sc;
                    *(float2*)(orow + col) = v;
                }
            }
        }
    }
}

// ---------------- exact GELU + LayerNorm (fp16 in/out, in place) ------------
__global__ __launch_bounds__(256) void gelu_ln_kernel()
{
    const float* ln_w = g_p[IX_LNW];
    const float* ln_b = g_p[IX_LNB];

    int slot = blockIdx.x;
    int e = g_eslot[slot];
    __half* h = g_hh + (size_t)slot * HDIM;
    const int PER = HDIM / 256;

    float vals[PER];
    float s = 0.f, s2 = 0.f;
#pragma unroll
    for (int i = 0; i < PER; i++) {
        int j = threadIdx.x + i * 256;
        float v = __half2float(h[j]);
        v = 0.5f * v * (1.0f + erff(v * 0.70710678118654752f));
        vals[i] = v;
        s += v; s2 += v * v;
    }
#pragma unroll
    for (int off = 16; off; off >>= 1) {
        s  += __shfl_xor_sync(0xffffffffu, s,  off);
        s2 += __shfl_xor_sync(0xffffffffu, s2, off);
    }
    __shared__ float shs[8], shs2[8];
    __shared__ float sh_mean, sh_inv;
    int wid = threadIdx.x >> 5, lane = threadIdx.x & 31;
    if (lane == 0) { shs[wid] = s; shs2[wid] = s2; }
    __syncthreads();
    if (threadIdx.x == 0) {
        float ts = 0.f, ts2 = 0.f;
#pragma unroll
        for (int w = 0; w < 8; w++) { ts += shs[w]; ts2 += shs2[w]; }
        float mean = ts * (1.0f / HDIM);
        float var  = ts2 * (1.0f / HDIM) - mean * mean;
        sh_mean = mean;
        sh_inv  = rsqrtf(var + LN_EPS);
    }
    __syncthreads();
    float mean = sh_mean, inv = sh_inv;
    const float* lw = ln_w + (size_t)e * HDIM;
    const float* lb = ln_b + (size_t)e * HDIM;
#pragma unroll
    for (int i = 0; i < PER; i++) {
        int j = threadIdx.x + i * 256;
        float o = (vals[i] - mean) * inv * lw[j] + lb[j];
        h[j] = __float2half_rn(o);
    }
}

// ---------------- combine ----------------
__global__ __launch_bounds__(256) void combine_kernel(float* __restrict__ out)
{
    int i = blockIdx.x * blockDim.x + threadIdx.x;
    if (i >= T_TOK * (DDIM / 4)) return;
    int t = i / (DDIM / 4);
    int j = (i % (DDIM / 4)) * 4;
    const float* yb = g_ybuf + ((size_t)t * NSLOT) * DDIM + j;
    float4 a = *(const float4*)(yb + 0 * DDIM);
    float4 b = *(const float4*)(yb + 1 * DDIM);
    float4 c = *(const float4*)(yb + 2 * DDIM);
    float4 d = *(const float4*)(yb + 3 * DDIM);
    float4 r;
    r.x = a.x + b.x + c.x + d.x;
    r.y = a.y + b.y + c.y + d.y;
    r.z = a.z + b.z + c.z + d.z;
    r.w = a.w + b.w + c.w + d.w;
    *(float4*)(out + (size_t)t * DDIM + j) = r;
}

// ---------------- launch ----------------
extern "C" void kernel_launch(void* const* d_in, const int* in_sizes, int n_in,
                              void* d_out, int out_size)
{
    InArgs a;
    int n = n_in < 9 ? n_in : 9;
    for (int i = 0; i < 9; i++) {
        a.p[i]  = (i < n) ? (const float*)d_in[i] : (const float*)d_in[n - 1];
        a.sz[i] = (i < n) ? in_sizes[i] : 0;
    }
    a.n = n;
    float* out = (float*)d_out;

    cudaFuncSetAttribute(expert_gemm<0>,
                         cudaFuncAttributeMaxDynamicSharedMemorySize, GEMM_SMEM);
    cudaFuncSetAttribute(expert_gemm<1>,
                         cudaFuncAttributeMaxDynamicSharedMemorySize, GEMM_SMEM);

    classify_kernel<<<1, 32>>>(a);
    gate_kernel<<<(T_TOK * 32) / 256, 256>>>();
    cvt_all_kernel<<<(2 * WQUARTS + XQUARTS + 255) / 256, 256>>>();

    expert_gemm<0><<<dim3(NEXP * MT, HDIM / BN), 256, GEMM_SMEM>>>(MT);
    gelu_ln_kernel<<<TOTSLOT, 256>>>();
    expert_gemm<1><<<dim3(NEXP * MT, DDIM / BN), 256, GEMM_SMEM>>>(MT);
    combine_kernel<<<(T_TOK * (DDIM / 4) + 255) / 256, 256>>>(out);
}